// round 9
// baseline (speedup 1.0000x reference)
#include <cuda_runtime.h>
#include <cuda_bf16.h>

// Problem constants (fixed shapes from setup_inputs)
#define B_DIM 8
#define T_DIM 4096
#define D_DIM 1024
#define K_FFT 64
#define F_DIM (K_FFT / 2 + 1)        // 33

#define NUM_CONV 128                 // B * D/64

// ---------------------------------------------------------------------------
// Conv kernel: per-(batch, 64-channel tile) filter build + register-resident
// circular convolution of the last K_FFT timesteps. min-blocks=1 so ptxas can
// use ~96 regs (fr[64] + acc[16] truly in registers; no local-memory spill).
// ---------------------------------------------------------------------------
__global__ void __launch_bounds__(256, 1) spectral_conv_kernel(
    const float* __restrict__ x, const float* __restrict__ mask,
    const float* __restrict__ mix_w, float* __restrict__ out)
{
    __shared__ float g_sh[64 * F_DIM];        // sigmoid(mask) tile [dl][f]
    __shared__ float tab[K_FFT];              // cos(2*pi*n/64)
    __shared__ float w_sh[K_FFT * 64];        // window [k][dl]
    __shared__ float f_sh[64 * (K_FFT + 1)];  // filter [dl][n], pad 65

    const int bid = blockIdx.x;
    const int tid = threadIdx.x;

    const int b  = bid >> 4;          // 0..7
    const int d0 = (bid & 15) * 64;   // channel tile base

    // Stage sigmoid(mask) for the 64 channels (2112 contiguous floats).
    const float* mrow = mask + (long long)d0 * F_DIM;
    for (int idx = tid; idx < 64 * F_DIM; idx += 256)
        g_sh[idx] = 1.0f / (1.0f + expf(-mrow[idx]));
    if (tid < K_FFT)
        tab[tid] = cospif((float)tid * (1.0f / 32.0f));   // exact twiddles

    // Stage the last-64-timestep window (coalesced).
    const float* xb = x + ((long long)b * T_DIM + (T_DIM - K_FFT)) * D_DIM + d0;
    #pragma unroll
    for (int i = 0; i < 16; i++) {
        int idx = tid + i * 256;
        int k = idx >> 6, dl = idx & 63;
        w_sh[idx] = xb[(long long)k * D_DIM + dl];
    }
    __syncthreads();

    // f[dl][n] = mix_w/64 * ( g0 + 2*sum_{f=1..31} g_f cos(2 pi f n/64) + g32*(-1)^n )
    #pragma unroll
    for (int i = 0; i < 16; i++) {
        int idx = tid + i * 256;
        int dl = idx >> 6, n = idx & 63;
        const float* gd = g_sh + dl * F_DIM;
        float s = gd[0] + gd[32] * tab[(32 * n) & 63];
        #pragma unroll
        for (int f = 1; f < 32; f++)
            s += 2.0f * gd[f] * tab[(f * n) & 63];
        f_sh[dl * 65 + n] = s * (1.0f / 64.0f) * mix_w[d0 + dl];
    }
    __syncthreads();

    const int dl = tid & 63;
    const int t0 = (tid >> 6) * 16;

    // Pre-rotated filter in registers: fr[i] = f[(t0+i)&63]
    //   -> y[t0+j] = sum_k w[k] * fr[(j-k)&63], all compile-time reg indices.
    float fr[K_FFT];
    #pragma unroll
    for (int i = 0; i < K_FFT; i++)
        fr[i] = f_sh[dl * 65 + ((t0 + i) & 63)];

    float acc[16];
    #pragma unroll
    for (int j = 0; j < 16; j++) acc[j] = 0.0f;

    #pragma unroll
    for (int k = 0; k < K_FFT; k++) {
        float wv = w_sh[k * 64 + dl];
        #pragma unroll
        for (int j = 0; j < 16; j++)
            acc[j] += wv * fr[(j - k + K_FFT) & 63];
    }

    float* ob = out + ((long long)b * T_DIM + (T_DIM - K_FFT)) * D_DIM + d0;
    #pragma unroll
    for (int j = 0; j < 16; j++)
        ob[(long long)(t0 + j) * D_DIM + dl] = acc[j];
}

// ---------------------------------------------------------------------------
// Launch: fork-join graph.
//   branch A (side stream): 8 per-batch memset nodes over rows [0, T-K)
//   branch B (main stream): conv kernel over the window rows (disjoint region)
// Side stream + events created once (host objects only; no device allocation).
// ---------------------------------------------------------------------------
static cudaStream_t g_side = nullptr;
static cudaEvent_t  g_fork = nullptr;
static cudaEvent_t  g_join = nullptr;

extern "C" void kernel_launch(void* const* d_in, const int* in_sizes, int n_in,
                              void* d_out, int out_size)
{
    const float* x     = (const float*)d_in[0];   // (B, T, D) fp32
    const float* mask  = (const float*)d_in[1];   // (D, 33)   fp32
    const float* mix_w = (const float*)d_in[2];   // (D,)      fp32
    float* out = (float*)d_out;                   // (B, T, D) fp32

    if (g_side == nullptr) {
        cudaStreamCreateWithFlags(&g_side, cudaStreamNonBlocking);
        cudaEventCreateWithFlags(&g_fork, cudaEventDisableTiming);
        cudaEventCreateWithFlags(&g_join, cudaEventDisableTiming);
    }

    // Fork: side stream joins the captured dependency chain.
    cudaEventRecord(g_fork, 0);
    cudaStreamWaitEvent(g_side, g_fork, 0);

    // Branch A: zero rows [0, T-K) of each batch (disjoint from conv writes).
    const size_t zbytes = (size_t)(T_DIM - K_FFT) * D_DIM * sizeof(float);
    for (int b = 0; b < B_DIM; b++)
        cudaMemsetAsync(out + (size_t)b * T_DIM * D_DIM, 0, zbytes, g_side);

    // Branch B: compute the last-64-timestep windows (runs concurrently).
    spectral_conv_kernel<<<NUM_CONV, 256, 0, 0>>>(x, mask, mix_w, out);

    // Join: main stream waits for the fill branch.
    cudaEventRecord(g_join, g_side);
    cudaStreamWaitEvent(0, g_join, 0);
}

// round 10
// speedup vs baseline: 1.1193x; 1.1193x over previous
#include <cuda_runtime.h>
#include <cuda_bf16.h>

// Problem constants (fixed shapes from setup_inputs)
#define B_DIM 8
#define T_DIM 4096
#define D_DIM 1024
#define K_FFT 64
#define F_DIM (K_FFT / 2 + 1)        // 33

#define NUM_CONV 128                 // B * D/64

// ---------------------------------------------------------------------------
// Conv kernel: per-(batch, 64-channel tile) filter build + register-resident
// circular convolution of the last K_FFT timesteps.
// Filter build uses the Chebyshev recurrence c_{f+1} = 2a c_f - c_{f-1}
// (a = cos(pi n / 32)) -> pure FFMA, no cosine-table LDS, no bank conflicts.
// ---------------------------------------------------------------------------
__global__ void __launch_bounds__(256, 1) spectral_conv_kernel(
    const float* __restrict__ x, const float* __restrict__ mask,
    const float* __restrict__ mix_w, float* __restrict__ out)
{
    __shared__ float gs_sh[64 * F_DIM];       // weighted sigmoid(mask) [dl][f]
    __shared__ float tab[K_FFT];              // a[n] = cos(pi n / 32)
    __shared__ float mw_sh[64];               // mix_w tile
    __shared__ float w_sh[K_FFT * 64];        // window [k][dl]
    __shared__ float f_sh[64 * (K_FFT + 1)];  // filter [dl][n], pad 65

    const int bid = blockIdx.x;
    const int tid = threadIdx.x;

    const int b  = bid >> 4;          // 0..7
    const int d0 = (bid & 15) * 64;   // channel tile base

    // Stage sigmoid(mask) with DFT weights folded in:
    //   gs[dl][0] = g0, gs[dl][f] = 2*g_f (f=1..31), gs[dl][32] = g32
    const float* mrow = mask + (long long)d0 * F_DIM;
    for (int idx = tid; idx < 64 * F_DIM; idx += 256) {
        int f = idx % F_DIM;          // idx = dl*33 + f (contiguous load)
        float g = 1.0f / (1.0f + expf(-mrow[idx]));
        float wgt = (f == 0 || f == 32) ? 1.0f : 2.0f;
        gs_sh[idx] = wgt * g;
    }
    if (tid < K_FFT)
        tab[tid] = cospif((float)tid * (1.0f / 32.0f));   // exact a[n]
    if (tid < 64)
        mw_sh[tid] = mix_w[d0 + tid] * (1.0f / 64.0f);

    // Stage the last-64-timestep window (coalesced).
    const float* xb = x + ((long long)b * T_DIM + (T_DIM - K_FFT)) * D_DIM + d0;
    #pragma unroll
    for (int i = 0; i < 16; i++) {
        int idx = tid + i * 256;
        int k = idx >> 6, dl = idx & 63;
        w_sh[idx] = xb[(long long)k * D_DIM + dl];
    }
    __syncthreads();

    // Build filter via Chebyshev recurrence (FFMA-only inner loop):
    //   f[dl][n] = (mix_w/64) * ( gs0 + sum_{f=1..31} gs_f * c_f + gs32 * c_32 )
    // gs reads are warp-uniform broadcasts; tab read is conflict-free.
    #pragma unroll
    for (int i = 0; i < 16; i++) {
        int idx = tid + i * 256;
        int dl = idx >> 6, n = idx & 63;
        const float* gd = gs_sh + dl * F_DIM;
        float a  = tab[n];
        float a2 = a + a;
        float cp = 1.0f, c = a;
        float s = gd[0];
        #pragma unroll
        for (int f = 1; f < 32; f++) {
            s = fmaf(gd[f], c, s);
            float cn = fmaf(a2, c, -cp);
            cp = c; c = cn;
        }
        s = fmaf(gd[32], c, s);       // c == cos(pi n) = (-1)^n
        f_sh[dl * 65 + n] = s * mw_sh[dl];
    }
    __syncthreads();

    const int dl = tid & 63;
    const int t0 = (tid >> 6) * 16;

    // Pre-rotated filter in registers: fr[i] = f[(t0+i)&63]
    //   -> y[t0+j] = sum_k w[k] * fr[(j-k)&63], all compile-time reg indices.
    float fr[K_FFT];
    #pragma unroll
    for (int i = 0; i < K_FFT; i++)
        fr[i] = f_sh[dl * 65 + ((t0 + i) & 63)];

    float acc[16];
    #pragma unroll
    for (int j = 0; j < 16; j++) acc[j] = 0.0f;

    #pragma unroll
    for (int k = 0; k < K_FFT; k++) {
        float wv = w_sh[k * 64 + dl];
        #pragma unroll
        for (int j = 0; j < 16; j++)
            acc[j] += wv * fr[(j - k + K_FFT) & 63];
    }

    float* ob = out + ((long long)b * T_DIM + (T_DIM - K_FFT)) * D_DIM + d0;
    #pragma unroll
    for (int j = 0; j < 16; j++)
        ob[(long long)(t0 + j) * D_DIM + dl] = acc[j];
}

// ---------------------------------------------------------------------------
// Launch: single memset node (proven ~6.7 TB/s driver fill) + conv kernel,
// serial on one stream. Two graph nodes, no events.
// ---------------------------------------------------------------------------
extern "C" void kernel_launch(void* const* d_in, const int* in_sizes, int n_in,
                              void* d_out, int out_size)
{
    const float* x     = (const float*)d_in[0];   // (B, T, D) fp32
    const float* mask  = (const float*)d_in[1];   // (D, 33)   fp32
    const float* mix_w = (const float*)d_in[2];   // (D,)      fp32
    float* out = (float*)d_out;                   // (B, T, D) fp32

    // Zero the entire output via the driver's fill path (one memset node).
    cudaMemsetAsync(out, 0, (size_t)out_size * sizeof(float), 0);

    // Compute the last-64-timestep windows (stream-ordered after the memset).
    spectral_conv_kernel<<<NUM_CONV, 256>>>(x, mask, mix_w, out);
}